// round 1
// baseline (speedup 1.0000x reference)
#include <cuda_runtime.h>
#include <cuda_bf16.h>
#include <math.h>

// Problem constants
#define BB 4
#define SS 1024
#define DD 1024
#define HH 16
#define HD 64
#define MLPD 4096
#define MODW 6144   // 6*D
#define LN_EPS 1e-5f

// ---------------- scratch (no allocs allowed) ----------------
__device__ float g_mod[BB * MODW];                       // 96 KB
__device__ float g_xm[(size_t)BB * SS * DD];             // 16 MB
__device__ float g_qkv[(size_t)BB * SS * 3 * DD];        // 48 MB
__device__ float g_attn[(size_t)BB * SS * DD];           // 16 MB
__device__ float g_x1[(size_t)BB * SS * DD];             // 16 MB
__device__ float g_h[(size_t)BB * SS * MLPD];            // 64 MB

// ---------------- adaLN modulation: mod = c @ adaLN_w + adaLN_b ----------------
__global__ void mod_kernel(const float* __restrict__ c, const float* __restrict__ w,
                           const float* __restrict__ bias, float* __restrict__ mod) {
    int n = blockIdx.x * blockDim.x + threadIdx.x;   // 0 .. B*6144-1
    if (n >= BB * MODW) return;
    int b = n / MODW;
    int col = n - b * MODW;
    float acc = bias[col];
    const float* cb = c + b * 128;
#pragma unroll 8
    for (int k = 0; k < 128; k++) acc = fmaf(cb[k], w[(size_t)k * MODW + col], acc);
    mod[n] = acc;
}

// ---------------- fused LayerNorm + modulate ----------------
// out[row][i] = ((x-mu)*rstd*w[i]) * (1 + mod[b, scaleSeg*D + i]) + mod[b, shiftSeg*D + i]
__global__ void ln_mod_kernel(const float* __restrict__ x, const float* __restrict__ w,
                              const float* __restrict__ mod, int shiftSeg, int scaleSeg,
                              float* __restrict__ out) {
    __shared__ float r1[256], r2[256];
    int row = blockIdx.x;            // 0 .. B*S-1
    int b = row >> 10;               // S = 1024
    int tid = threadIdx.x;
    const float* xr = x + (size_t)row * DD;
    float s = 0.f, ss = 0.f;
#pragma unroll
    for (int i = tid; i < DD; i += 256) {
        float v = xr[i];
        s += v; ss += v * v;
    }
    r1[tid] = s; r2[tid] = ss;
    __syncthreads();
    for (int o = 128; o > 0; o >>= 1) {
        if (tid < o) { r1[tid] += r1[tid + o]; r2[tid] += r2[tid + o]; }
        __syncthreads();
    }
    float mu = r1[0] * (1.0f / DD);
    float var = r2[0] * (1.0f / DD) - mu * mu;
    float rstd = rsqrtf(var + LN_EPS);
    const float* sh = mod + (size_t)b * MODW + shiftSeg * DD;
    const float* sc = mod + (size_t)b * MODW + scaleSeg * DD;
    float* orow = out + (size_t)row * DD;
#pragma unroll
    for (int i = tid; i < DD; i += 256) {
        float y = (xr[i] - mu) * rstd * w[i];
        orow[i] = fmaf(y, 1.0f + sc[i], sh[i]);
    }
}

// ---------------- GELU (tanh approx) ----------------
__device__ __forceinline__ float gelu_tanh(float x) {
    float x3 = x * x * x;
    return 0.5f * x * (1.0f + tanhf(0.7978845608028654f * (x + 0.044715f * x3)));
}

// ---------------- SGEMM 128x128x8, 256 threads, 8x8 per thread ----------------
// EPI 0: C = acc
// EPI 1: C = gelu(acc + bias[col])
// EPI 2: C = resid[row*N+col] + mod[(row>>10)*6144 + modOff + col] * (acc + bias?)
template<int EPI>
__global__ __launch_bounds__(256, 2)
void sgemm128(const float* __restrict__ A, const float* __restrict__ B,
              const float* __restrict__ bias, const float* __restrict__ resid,
              const float* __restrict__ mod, int modOff,
              float* __restrict__ C, int M, int N, int K) {
    __shared__ float As[8][128];
    __shared__ float Bs[8][128];
    int tid = threadIdx.x;
    int bx = blockIdx.x, by = blockIdx.y;

    int aRow = tid >> 1;
    int aCol = (tid & 1) * 4;
    int bRow = tid >> 5;
    int bCol = (tid & 31) * 4;
    const float* Ab = A + ((size_t)(by * 128 + aRow)) * K + aCol;
    const float* Bb = B + (size_t)bRow * N + bx * 128 + bCol;

    int tx = tid & 15, ty = tid >> 4;
    float acc[8][8];
#pragma unroll
    for (int i = 0; i < 8; i++)
#pragma unroll
        for (int j = 0; j < 8; j++) acc[i][j] = 0.f;

    for (int k0 = 0; k0 < K; k0 += 8) {
        float4 av = *(const float4*)(Ab + k0);
        float4 bv = *(const float4*)(Bb + (size_t)k0 * N);
        __syncthreads();
        As[aCol + 0][aRow] = av.x;
        As[aCol + 1][aRow] = av.y;
        As[aCol + 2][aRow] = av.z;
        As[aCol + 3][aRow] = av.w;
        *(float4*)&Bs[bRow][bCol] = bv;
        __syncthreads();
#pragma unroll
        for (int k = 0; k < 8; k++) {
            float a[8], bb[8];
            *(float4*)(a)     = *(const float4*)&As[k][ty * 8];
            *(float4*)(a + 4) = *(const float4*)&As[k][ty * 8 + 4];
            *(float4*)(bb)     = *(const float4*)&Bs[k][tx * 8];
            *(float4*)(bb + 4) = *(const float4*)&Bs[k][tx * 8 + 4];
#pragma unroll
            for (int i = 0; i < 8; i++)
#pragma unroll
                for (int j = 0; j < 8; j++)
                    acc[i][j] = fmaf(a[i], bb[j], acc[i][j]);
        }
    }

#pragma unroll
    for (int i = 0; i < 8; i++) {
        int row = by * 128 + ty * 8 + i;
        size_t rowBase = (size_t)row * N;
#pragma unroll
        for (int j = 0; j < 8; j++) {
            int col = bx * 128 + tx * 8 + j;
            float v = acc[i][j];
            if (EPI == 0) {
                C[rowBase + col] = v;
            } else if (EPI == 1) {
                v += bias[col];
                C[rowBase + col] = gelu_tanh(v);
            } else {
                if (bias) v += bias[col];
                float g = mod[(size_t)(row >> 10) * MODW + modOff + col];
                C[rowBase + col] = fmaf(g, v, resid[rowBase + col]);
            }
        }
    }
}

// ---------------- RoPE on q and k (in place in g_qkv) ----------------
__global__ void rope_kernel(float* __restrict__ qkv, const float* __restrict__ cosb,
                            const float* __restrict__ sinb) {
    int id = blockIdx.x * blockDim.x + threadIdx.x;   // B*S*2*H*32 = 4194304
    if (id >= BB * SS * 2 * HH * 32) return;
    int e = id & 31;
    int h = (id >> 5) & 15;
    int sel = (id >> 9) & 1;        // 0 = q, 1 = k
    int bs = id >> 10;              // b*S + s
    int s = bs & (SS - 1);
    size_t base = (size_t)bs * 3072 + (size_t)sel * 1024 + h * 64;
    float t1 = qkv[base + e];
    float t2 = qkv[base + e + 32];
    float cv = cosb[s * 32 + e];
    float sv = sinb[s * 32 + e];
    qkv[base + e]      = t1 * cv - t2 * sv;
    qkv[base + e + 32] = t2 * cv + t1 * sv;
}

// ---------------- attention: flash-style, fp32 ----------------
// grid: (B*H, S/64), block: 256 (8 warps x 8 query rows each), 64-key tiles
#define ATTN_SMEM_BYTES ((4096 + 4096 + 64*65 + 4096) * 4)
__global__ __launch_bounds__(256, 2)
void attn_kernel(const float* __restrict__ qkv, float* __restrict__ out) {
    int b = blockIdx.x >> 4;
    int h = blockIdx.x & 15;
    int q0 = blockIdx.y * 64;
    int tid = threadIdx.x, w = tid >> 5, l = tid & 31;
    extern __shared__ float sm[];
    float* Qs = sm;                 // [64 q][64 d]
    float* Ps = sm + 4096;          // [64 q][64 key]
    float* Ks = sm + 8192;          // [64 key][65]
    float* Vs = sm + 8192 + 64 * 65;// [64 key][64 d]
    size_t bS = (size_t)b * SS;

    // load Q tile, pre-scaled by 1/sqrt(HD)
    for (int i = tid * 4; i < 4096; i += 1024) {
        int qi = i >> 6, d = i & 63;
        float4 v = *(const float4*)(qkv + (bS + q0 + qi) * 3072 + h * 64 + d);
        v.x *= 0.125f; v.y *= 0.125f; v.z *= 0.125f; v.w *= 0.125f;
        *(float4*)&Qs[i] = v;
    }

    float o0[8], o1[8], mrow[8], lrow[8];
#pragma unroll
    for (int r = 0; r < 8; r++) { o0[r] = 0.f; o1[r] = 0.f; mrow[r] = -1e30f; lrow[r] = 0.f; }

    for (int kb = 0; kb < SS; kb += 64) {
        __syncthreads();
        // stage K (padded stride 65) and V
        for (int i = tid * 4; i < 4096; i += 1024) {
            int j = i >> 6, d = i & 63;
            const float* kp = qkv + (bS + kb + j) * 3072 + 1024 + h * 64 + d;
            float4 kv = *(const float4*)kp;
            Ks[j * 65 + d]     = kv.x;
            Ks[j * 65 + d + 1] = kv.y;
            Ks[j * 65 + d + 2] = kv.z;
            Ks[j * 65 + d + 3] = kv.w;
            float4 vv = *(const float4*)(kp + 1024);
            *(float4*)&Vs[j * 64 + d] = vv;
        }
        __syncthreads();

        // scores: lane l owns keys l and l+32
        float s0[8], s1[8];
#pragma unroll
        for (int r = 0; r < 8; r++) { s0[r] = 0.f; s1[r] = 0.f; }
        const float* KsA = Ks + l * 65;
        const float* KsB = Ks + (l + 32) * 65;
#pragma unroll 4
        for (int d = 0; d < 64; d += 4) {
            float ka0 = KsA[d], ka1 = KsA[d + 1], ka2 = KsA[d + 2], ka3 = KsA[d + 3];
            float kb0 = KsB[d], kb1 = KsB[d + 1], kb2 = KsB[d + 2], kb3 = KsB[d + 3];
#pragma unroll
            for (int r = 0; r < 8; r++) {
                float4 q = *(const float4*)&Qs[(w * 8 + r) * 64 + d];
                s0[r] = fmaf(q.x, ka0, fmaf(q.y, ka1, fmaf(q.z, ka2, fmaf(q.w, ka3, s0[r]))));
                s1[r] = fmaf(q.x, kb0, fmaf(q.y, kb1, fmaf(q.z, kb2, fmaf(q.w, kb3, s1[r]))));
            }
        }

        // online softmax per row
#pragma unroll
        for (int r = 0; r < 8; r++) {
            float tm = fmaxf(s0[r], s1[r]);
#pragma unroll
            for (int o = 16; o > 0; o >>= 1) tm = fmaxf(tm, __shfl_xor_sync(0xffffffffu, tm, o));
            float nm = fmaxf(mrow[r], tm);
            float corr = __expf(mrow[r] - nm);
            float p0 = __expf(s0[r] - nm);
            float p1 = __expf(s1[r] - nm);
            float ps = p0 + p1;
#pragma unroll
            for (int o = 16; o > 0; o >>= 1) ps += __shfl_xor_sync(0xffffffffu, ps, o);
            lrow[r] = lrow[r] * corr + ps;
            o0[r] *= corr; o1[r] *= corr;
            mrow[r] = nm;
            Ps[(w * 8 + r) * 64 + l]      = p0;
            Ps[(w * 8 + r) * 64 + l + 32] = p1;
        }
        __syncwarp();

        // P @ V: lane l owns output dims (2l, 2l+1)
#pragma unroll 4
        for (int j = 0; j < 64; j += 4) {
            float2 v0 = *(const float2*)&Vs[j * 64 + 2 * l];
            float2 v1 = *(const float2*)&Vs[(j + 1) * 64 + 2 * l];
            float2 v2 = *(const float2*)&Vs[(j + 2) * 64 + 2 * l];
            float2 v3 = *(const float2*)&Vs[(j + 3) * 64 + 2 * l];
#pragma unroll
            for (int r = 0; r < 8; r++) {
                float4 p = *(const float4*)&Ps[(w * 8 + r) * 64 + j];
                o0[r] = fmaf(p.x, v0.x, fmaf(p.y, v1.x, fmaf(p.z, v2.x, fmaf(p.w, v3.x, o0[r]))));
                o1[r] = fmaf(p.x, v0.y, fmaf(p.y, v1.y, fmaf(p.z, v2.y, fmaf(p.w, v3.y, o1[r]))));
            }
        }
    }

#pragma unroll
    for (int r = 0; r < 8; r++) {
        float inv = 1.0f / lrow[r];
        size_t row = bS + q0 + w * 8 + r;
        out[row * 1024 + h * 64 + 2 * l]     = o0[r] * inv;
        out[row * 1024 + h * 64 + 2 * l + 1] = o1[r] * inv;
    }
}

// ---------------- launch ----------------
extern "C" void kernel_launch(void* const* d_in, const int* in_sizes, int n_in,
                              void* d_out, int out_size) {
    const float* x       = (const float*)d_in[0];
    const float* c       = (const float*)d_in[1];
    const float* norm1_w = (const float*)d_in[2];
    const float* norm2_w = (const float*)d_in[3];
    const float* w_qkv   = (const float*)d_in[4];
    const float* w_out   = (const float*)d_in[5];
    const float* w1      = (const float*)d_in[6];
    const float* b1      = (const float*)d_in[7];
    const float* w2      = (const float*)d_in[8];
    const float* b2      = (const float*)d_in[9];
    const float* adaLN_w = (const float*)d_in[10];
    const float* adaLN_b = (const float*)d_in[11];
    const float* cosb    = (const float*)d_in[12];
    const float* sinb    = (const float*)d_in[13];
    float* out = (float*)d_out;

    float *mod, *xm, *qkv, *attn, *x1, *hbuf;
    cudaGetSymbolAddress((void**)&mod,  g_mod);
    cudaGetSymbolAddress((void**)&xm,   g_xm);
    cudaGetSymbolAddress((void**)&qkv,  g_qkv);
    cudaGetSymbolAddress((void**)&attn, g_attn);
    cudaGetSymbolAddress((void**)&x1,   g_x1);
    cudaGetSymbolAddress((void**)&hbuf, g_h);

    cudaFuncSetAttribute(attn_kernel, cudaFuncAttributeMaxDynamicSharedMemorySize,
                         ATTN_SMEM_BYTES);

    // 1) adaLN modulation vector
    mod_kernel<<<(BB * MODW + 255) / 256, 256>>>(c, adaLN_w, adaLN_b, mod);

    // 2) LN1 + modulate (shift_msa = seg0, scale_msa = seg1)
    ln_mod_kernel<<<BB * SS, 256>>>(x, norm1_w, mod, 0, 1, xm);

    // 3) QKV GEMM: [4096,1024] x [1024,3072]
    sgemm128<0><<<dim3(3072 / 128, 4096 / 128), 256>>>(
        xm, w_qkv, nullptr, nullptr, nullptr, 0, qkv, BB * SS, 3 * DD, DD);

    // 4) RoPE in place on q,k
    rope_kernel<<<(BB * SS * 2 * HH * 32) / 256, 256>>>(qkv, cosb, sinb);

    // 5) attention
    attn_kernel<<<dim3(BB * HH, SS / 64), 256, ATTN_SMEM_BYTES>>>(qkv, attn);

    // 6) out-proj + gated residual: x1 = x + gate_msa (seg2) * (attn @ w_out)
    sgemm128<2><<<dim3(1024 / 128, 4096 / 128), 256>>>(
        attn, w_out, nullptr, x, mod, 2 * DD, x1, BB * SS, DD, DD);

    // 7) LN2 + modulate (shift_mlp = seg3, scale_mlp = seg4)
    ln_mod_kernel<<<BB * SS, 256>>>(x1, norm2_w, mod, 3, 4, xm);

    // 8) MLP up + GELU: h = gelu(xm @ w1 + b1)
    sgemm128<1><<<dim3(MLPD / 128, 4096 / 128), 256>>>(
        xm, w1, b1, nullptr, nullptr, 0, hbuf, BB * SS, MLPD, DD);

    // 9) MLP down + gated residual: out = x1 + gate_mlp (seg5) * (h @ w2 + b2)
    sgemm128<2><<<dim3(1024 / 128, 4096 / 128), 256>>>(
        hbuf, w2, b2, x1, mod, 5 * DD, out, BB * SS, DD, MLPD);
}

// round 5
// speedup vs baseline: 2.0410x; 2.0410x over previous
#include <cuda_runtime.h>
#include <cuda_bf16.h>
#include <cstdint>
#include <math.h>

// Problem constants
#define BB 4
#define SS 1024
#define DD 1024
#define HH 16
#define HD 64
#define MLPD 4096
#define MODW 6144   // 6*D
#define LN_EPS 1e-5f

// ---------------- scratch (no allocs allowed) ----------------
__device__ float g_mod[BB * MODW];
__device__ float g_xm[(size_t)BB * SS * DD];
__device__ float g_qkv[(size_t)BB * SS * 3 * DD];
__device__ float g_attn[(size_t)BB * SS * DD];
__device__ float g_x1[(size_t)BB * SS * DD];
__device__ float g_h[(size_t)BB * SS * MLPD];

// ---------------- adaLN modulation: mod = c @ adaLN_w + adaLN_b ----------------
__global__ void mod_kernel(const float* __restrict__ c, const float* __restrict__ w,
                           const float* __restrict__ bias, float* __restrict__ mod) {
    int n = blockIdx.x * blockDim.x + threadIdx.x;
    if (n >= BB * MODW) return;
    int b = n / MODW;
    int col = n - b * MODW;
    float acc = bias[col];
    const float* cb = c + b * 128;
#pragma unroll 8
    for (int k = 0; k < 128; k++) acc = fmaf(cb[k], w[(size_t)k * MODW + col], acc);
    mod[n] = acc;
}

// ---------------- fused LayerNorm + modulate ----------------
__global__ void ln_mod_kernel(const float* __restrict__ x, const float* __restrict__ w,
                              const float* __restrict__ mod, int shiftSeg, int scaleSeg,
                              float* __restrict__ out) {
    __shared__ float r1[256], r2[256];
    int row = blockIdx.x;
    int b = row >> 10;
    int tid = threadIdx.x;
    const float* xr = x + (size_t)row * DD;
    float s = 0.f, ss = 0.f;
#pragma unroll
    for (int i = tid; i < DD; i += 256) {
        float v = xr[i];
        s += v; ss += v * v;
    }
    r1[tid] = s; r2[tid] = ss;
    __syncthreads();
    for (int o = 128; o > 0; o >>= 1) {
        if (tid < o) { r1[tid] += r1[tid + o]; r2[tid] += r2[tid + o]; }
        __syncthreads();
    }
    float mu = r1[0] * (1.0f / DD);
    float var = r2[0] * (1.0f / DD) - mu * mu;
    float rstd = rsqrtf(var + LN_EPS);
    const float* sh = mod + (size_t)b * MODW + shiftSeg * DD;
    const float* sc = mod + (size_t)b * MODW + scaleSeg * DD;
    float* orow = out + (size_t)row * DD;
#pragma unroll
    for (int i = tid; i < DD; i += 256) {
        float y = (xr[i] - mu) * rstd * w[i];
        orow[i] = fmaf(y, 1.0f + sc[i], sh[i]);
    }
}

__device__ __forceinline__ float gelu_tanh(float x) {
    float x3 = x * x * x;
    return 0.5f * x * (1.0f + tanhf(0.7978845608028654f * (x + 0.044715f * x3)));
}

__device__ __forceinline__ float to_tf32(float x) {
    unsigned int u;
    asm("cvt.rna.tf32.f32 %0, %1;" : "=r"(u) : "f"(x));
    return __uint_as_float(u);
}

__device__ __forceinline__ void mma_tf32(float c[4], unsigned int a0, unsigned int a1,
                                         unsigned int a2, unsigned int a3,
                                         unsigned int b0, unsigned int b1) {
    asm volatile("mma.sync.aligned.m16n8k8.row.col.f32.tf32.tf32.f32 "
                 "{%0,%1,%2,%3}, {%4,%5,%6,%7}, {%8,%9}, {%0,%1,%2,%3};"
                 : "+f"(c[0]), "+f"(c[1]), "+f"(c[2]), "+f"(c[3])
                 : "r"(a0), "r"(a1), "r"(a2), "r"(a3), "r"(b0), "r"(b1));
}

// ---------------- TF32 tensor-core GEMM ----------------
// 128x128 CTA tile, K-stage 32, double-buffered smem, 8 warps (2x4), warp = 64x32.
// smem per buffer: As[32][136] + Bs[32][136] (k-major, pad 136 -> conflict-free frags)
// EPI 0: C = acc
// EPI 1: C = gelu(acc + bias[col])
// EPI 2: C = resid + mod[(row>>10)*6144 + modOff + col] * (acc + bias?)
#define GSM_STRIDE 136
#define GSM_BUF (2 * 32 * GSM_STRIDE)            // floats per buffer (A+B)
#define GSM_BYTES (2 * GSM_BUF * 4)              // 69632 B dynamic smem

template<int EPI>
__global__ __launch_bounds__(256, 2)
void tgemm(const float* __restrict__ A, const float* __restrict__ B,
           const float* __restrict__ bias, const float* __restrict__ resid,
           const float* __restrict__ mod, int modOff,
           float* __restrict__ C, int M, int N, int K) {
    extern __shared__ float smf[];
    const int tid = threadIdx.x;
    const int lane = tid & 31, wid = tid >> 5;
    const int gid = lane >> 2, tig = lane & 3;
    const int bx = blockIdx.x, by = blockIdx.y;
    const int m0w = (wid >> 2) * 64;   // warp row offset in tile
    const int n0w = (wid & 3) * 32;    // warp col offset in tile

    // Global load mapping: A rows, 2 threads/row, 4 float4 each
    const int am = tid >> 1;
    const int akq = (tid & 1) * 4;     // float4 index base within 8
    const float* Ag = A + (size_t)(by * 128 + am) * K + akq * 4;

    float acc[4][4][4];
#pragma unroll
    for (int i = 0; i < 4; i++)
#pragma unroll
        for (int j = 0; j < 4; j++)
#pragma unroll
            for (int r = 0; r < 4; r++) acc[i][j][r] = 0.f;

    const int NS = K >> 5;
    float4 pa[4], pb[4];

    // ---- stage load (global -> regs) ----
    auto loadG = [&](int ks) {
#pragma unroll
        for (int e = 0; e < 4; e++)
            pa[e] = *(const float4*)(Ag + ks * 32 + e * 4);
#pragma unroll
        for (int e = 0; e < 4; e++) {
            int idx = tid + e * 256;
            int k = idx >> 5, nq = idx & 31;
            pb[e] = *(const float4*)(B + (size_t)(ks * 32 + k) * N + bx * 128 + nq * 4);
        }
    };
    // ---- stage store (regs -> smem, with tf32 rounding) ----
    auto storeS = [&](int buf) {
        float* As = smf + buf * GSM_BUF;
        float* Bs = As + 32 * GSM_STRIDE;
#pragma unroll
        for (int e = 0; e < 4; e++) {
            int kb = (akq + e) * 4;
            As[(kb + 0) * GSM_STRIDE + am] = to_tf32(pa[e].x);
            As[(kb + 1) * GSM_STRIDE + am] = to_tf32(pa[e].y);
            As[(kb + 2) * GSM_STRIDE + am] = to_tf32(pa[e].z);
            As[(kb + 3) * GSM_STRIDE + am] = to_tf32(pa[e].w);
        }
#pragma unroll
        for (int e = 0; e < 4; e++) {
            int idx = tid + e * 256;
            int k = idx >> 5, nq = idx & 31;
            float4 v;
            v.x = to_tf32(pb[e].x); v.y = to_tf32(pb[e].y);
            v.z = to_tf32(pb[e].z); v.w = to_tf32(pb[e].w);
            *(float4*)&Bs[k * GSM_STRIDE + nq * 4] = v;
        }
    };

    loadG(0);
    storeS(0);
    __syncthreads();

    for (int ks = 0; ks < NS; ks++) {
        if (ks + 1 < NS) loadG(ks + 1);
        const float* As = smf + (ks & 1) * GSM_BUF;
        const float* Bs = As + 32 * GSM_STRIDE;
#pragma unroll
        for (int t = 0; t < 4; t++) {
            const int kb = t * 8;
            unsigned int af[4][4], bf[4][2];
#pragma unroll
            for (int mt = 0; mt < 4; mt++)
#pragma unroll
                for (int r = 0; r < 4; r++)
                    af[mt][r] = __float_as_uint(
                        As[(kb + tig + 4 * (r >> 1)) * GSM_STRIDE + m0w + mt * 16 + gid + 8 * (r & 1)]);
#pragma unroll
            for (int nt = 0; nt < 4; nt++)
#pragma unroll
                for (int r = 0; r < 2; r++)
                    bf[nt][r] = __float_as_uint(
                        Bs[(kb + tig + 4 * r) * GSM_STRIDE + n0w + nt * 8 + gid]);
#pragma unroll
            for (int mt = 0; mt < 4; mt++)
#pragma unroll
                for (int nt = 0; nt < 4; nt++)
                    mma_tf32(acc[mt][nt], af[mt][0], af[mt][1], af[mt][2], af[mt][3],
                             bf[nt][0], bf[nt][1]);
        }
        if (ks + 1 < NS) {
            storeS((ks + 1) & 1);
            __syncthreads();
        }
    }

    // ---- epilogue ----
#pragma unroll
    for (int mt = 0; mt < 4; mt++) {
#pragma unroll
        for (int half = 0; half < 2; half++) {
            int row = by * 128 + m0w + mt * 16 + gid + 8 * half;
            size_t rowBase = (size_t)row * N;
#pragma unroll
            for (int nt = 0; nt < 4; nt++) {
                int col = bx * 128 + n0w + nt * 8 + 2 * tig;
                float v0 = acc[mt][nt][2 * half];
                float v1 = acc[mt][nt][2 * half + 1];
                if (EPI == 0) {
                    *(float2*)&C[rowBase + col] = make_float2(v0, v1);
                } else if (EPI == 1) {
                    v0 = gelu_tanh(v0 + bias[col]);
                    v1 = gelu_tanh(v1 + bias[col + 1]);
                    *(float2*)&C[rowBase + col] = make_float2(v0, v1);
                } else {
                    if (bias) { v0 += bias[col]; v1 += bias[col + 1]; }
                    size_t mb = (size_t)(row >> 10) * MODW + modOff + col;
                    float g0 = mod[mb], g1 = mod[mb + 1];
                    float2 rr = *(const float2*)&resid[rowBase + col];
                    *(float2*)&C[rowBase + col] =
                        make_float2(fmaf(g0, v0, rr.x), fmaf(g1, v1, rr.y));
                }
            }
        }
    }
}

// ---------------- RoPE on q and k (in place in g_qkv) ----------------
__global__ void rope_kernel(float* __restrict__ qkv, const float* __restrict__ cosb,
                            const float* __restrict__ sinb) {
    int id = blockIdx.x * blockDim.x + threadIdx.x;
    if (id >= BB * SS * 2 * HH * 32) return;
    int e = id & 31;
    int h = (id >> 5) & 15;
    int sel = (id >> 9) & 1;
    int bs = id >> 10;
    int s = bs & (SS - 1);
    size_t base = (size_t)bs * 3072 + (size_t)sel * 1024 + h * 64;
    float t1 = qkv[base + e];
    float t2 = qkv[base + e + 32];
    float cv = cosb[s * 32 + e];
    float sv = sinb[s * 32 + e];
    qkv[base + e]      = t1 * cv - t2 * sv;
    qkv[base + e + 32] = t2 * cv + t1 * sv;
}

// ---------------- attention: flash-style, fp32 ----------------
#define ATTN_SMEM_BYTES ((4096 + 4096 + 64*65 + 4096) * 4)
__global__ __launch_bounds__(256, 2)
void attn_kernel(const float* __restrict__ qkv, float* __restrict__ out) {
    int b = blockIdx.x >> 4;
    int h = blockIdx.x & 15;
    int q0 = blockIdx.y * 64;
    int tid = threadIdx.x, w = tid >> 5, l = tid & 31;
    extern __shared__ float sm[];
    float* Qs = sm;
    float* Ps = sm + 4096;
    float* Ks = sm + 8192;
    float* Vs = sm + 8192 + 64 * 65;
    size_t bS = (size_t)b * SS;

    for (int i = tid * 4; i < 4096; i += 1024) {
        int qi = i >> 6, d = i & 63;
        float4 v = *(const float4*)(qkv + (bS + q0 + qi) * 3072 + h * 64 + d);
        v.x *= 0.125f; v.y *= 0.125f; v.z *= 0.125f; v.w *= 0.125f;
        *(float4*)&Qs[i] = v;
    }

    float o0[8], o1[8], mrow[8], lrow[8];
#pragma unroll
    for (int r = 0; r < 8; r++) { o0[r] = 0.f; o1[r] = 0.f; mrow[r] = -1e30f; lrow[r] = 0.f; }

    for (int kb = 0; kb < SS; kb += 64) {
        __syncthreads();
        for (int i = tid * 4; i < 4096; i += 1024) {
            int j = i >> 6, d = i & 63;
            const float* kp = qkv + (bS + kb + j) * 3072 + 1024 + h * 64 + d;
            float4 kv = *(const float4*)kp;
            Ks[j * 65 + d]     = kv.x;
            Ks[j * 65 + d + 1] = kv.y;
            Ks[j * 65 + d + 2] = kv.z;
            Ks[j * 65 + d + 3] = kv.w;
            float4 vv = *(const float4*)(kp + 1024);
            *(float4*)&Vs[j * 64 + d] = vv;
        }
        __syncthreads();

        float s0[8], s1[8];
#pragma unroll
        for (int r = 0; r < 8; r++) { s0[r] = 0.f; s1[r] = 0.f; }
        const float* KsA = Ks + l * 65;
        const float* KsB = Ks + (l + 32) * 65;
#pragma unroll 4
        for (int d = 0; d < 64; d += 4) {
            float ka0 = KsA[d], ka1 = KsA[d + 1], ka2 = KsA[d + 2], ka3 = KsA[d + 3];
            float kb0 = KsB[d], kb1 = KsB[d + 1], kb2 = KsB[d + 2], kb3 = KsB[d + 3];
#pragma unroll
            for (int r = 0; r < 8; r++) {
                float4 q = *(const float4*)&Qs[(w * 8 + r) * 64 + d];
                s0[r] = fmaf(q.x, ka0, fmaf(q.y, ka1, fmaf(q.z, ka2, fmaf(q.w, ka3, s0[r]))));
                s1[r] = fmaf(q.x, kb0, fmaf(q.y, kb1, fmaf(q.z, kb2, fmaf(q.w, kb3, s1[r]))));
            }
        }

#pragma unroll
        for (int r = 0; r < 8; r++) {
            float tm = fmaxf(s0[r], s1[r]);
#pragma unroll
            for (int o = 16; o > 0; o >>= 1) tm = fmaxf(tm, __shfl_xor_sync(0xffffffffu, tm, o));
            float nm = fmaxf(mrow[r], tm);
            float corr = __expf(mrow[r] - nm);
            float p0 = __expf(s0[r] - nm);
            float p1 = __expf(s1[r] - nm);
            float ps = p0 + p1;
#pragma unroll
            for (int o = 16; o > 0; o >>= 1) ps += __shfl_xor_sync(0xffffffffu, ps, o);
            lrow[r] = lrow[r] * corr + ps;
            o0[r] *= corr; o1[r] *= corr;
            mrow[r] = nm;
            Ps[(w * 8 + r) * 64 + l]      = p0;
            Ps[(w * 8 + r) * 64 + l + 32] = p1;
        }
        __syncwarp();

#pragma unroll 4
        for (int j = 0; j < 64; j += 4) {
            float2 v0 = *(const float2*)&Vs[j * 64 + 2 * l];
            float2 v1 = *(const float2*)&Vs[(j + 1) * 64 + 2 * l];
            float2 v2 = *(const float2*)&Vs[(j + 2) * 64 + 2 * l];
            float2 v3 = *(const float2*)&Vs[(j + 3) * 64 + 2 * l];
#pragma unroll
            for (int r = 0; r < 8; r++) {
                float4 p = *(const float4*)&Ps[(w * 8 + r) * 64 + j];
                o0[r] = fmaf(p.x, v0.x, fmaf(p.y, v1.x, fmaf(p.z, v2.x, fmaf(p.w, v3.x, o0[r]))));
                o1[r] = fmaf(p.x, v0.y, fmaf(p.y, v1.y, fmaf(p.z, v2.y, fmaf(p.w, v3.y, o1[r]))));
            }
        }
    }

#pragma unroll
    for (int r = 0; r < 8; r++) {
        float inv = 1.0f / lrow[r];
        size_t row = bS + q0 + w * 8 + r;
        out[row * 1024 + h * 64 + 2 * l]     = o0[r] * inv;
        out[row * 1024 + h * 64 + 2 * l + 1] = o1[r] * inv;
    }
}

// ---------------- launch ----------------
extern "C" void kernel_launch(void* const* d_in, const int* in_sizes, int n_in,
                              void* d_out, int out_size) {
    const float* x       = (const float*)d_in[0];
    const float* c       = (const float*)d_in[1];
    const float* norm1_w = (const float*)d_in[2];
    const float* norm2_w = (const float*)d_in[3];
    const float* w_qkv   = (const float*)d_in[4];
    const float* w_out   = (const float*)d_in[5];
    const float* w1      = (const float*)d_in[6];
    const float* b1      = (const float*)d_in[7];
    const float* w2      = (const float*)d_in[8];
    const float* b2      = (const float*)d_in[9];
    const float* adaLN_w = (const float*)d_in[10];
    const float* adaLN_b = (const float*)d_in[11];
    const float* cosb    = (const float*)d_in[12];
    const float* sinb    = (const float*)d_in[13];
    float* out = (float*)d_out;

    float *mod, *xm, *qkv, *attn, *x1, *hbuf;
    cudaGetSymbolAddress((void**)&mod,  g_mod);
    cudaGetSymbolAddress((void**)&xm,   g_xm);
    cudaGetSymbolAddress((void**)&qkv,  g_qkv);
    cudaGetSymbolAddress((void**)&attn, g_attn);
    cudaGetSymbolAddress((void**)&x1,   g_x1);
    cudaGetSymbolAddress((void**)&hbuf, g_h);

    cudaFuncSetAttribute(attn_kernel, cudaFuncAttributeMaxDynamicSharedMemorySize,
                         ATTN_SMEM_BYTES);
    cudaFuncSetAttribute(tgemm<0>, cudaFuncAttributeMaxDynamicSharedMemorySize, GSM_BYTES);
    cudaFuncSetAttribute(tgemm<1>, cudaFuncAttributeMaxDynamicSharedMemorySize, GSM_BYTES);
    cudaFuncSetAttribute(tgemm<2>, cudaFuncAttributeMaxDynamicSharedMemorySize, GSM_BYTES);

    // 1) adaLN modulation vector
    mod_kernel<<<(BB * MODW + 255) / 256, 256>>>(c, adaLN_w, adaLN_b, mod);

    // 2) LN1 + modulate (shift_msa = seg0, scale_msa = seg1)
    ln_mod_kernel<<<BB * SS, 256>>>(x, norm1_w, mod, 0, 1, xm);

    // 3) QKV GEMM: [4096,1024] x [1024,3072]
    tgemm<0><<<dim3(3072 / 128, 4096 / 128), 256, GSM_BYTES>>>(
        xm, w_qkv, nullptr, nullptr, nullptr, 0, qkv, BB * SS, 3 * DD, DD);

    // 4) RoPE in place on q,k
    rope_kernel<<<(BB * SS * 2 * HH * 32) / 256, 256>>>(qkv, cosb, sinb);

    // 5) attention
    attn_kernel<<<dim3(BB * HH, SS / 64), 256, ATTN_SMEM_BYTES>>>(qkv, attn);

    // 6) out-proj + gated residual: x1 = x + gate_msa (seg2) * (attn @ w_out)
    tgemm<2><<<dim3(1024 / 128, 4096 / 128), 256, GSM_BYTES>>>(
        attn, w_out, nullptr, x, mod, 2 * DD, x1, BB * SS, DD, DD);

    // 7) LN2 + modulate (shift_mlp = seg3, scale_mlp = seg4)
    ln_mod_kernel<<<BB * SS, 256>>>(x1, norm2_w, mod, 3, 4, xm);

    // 8) MLP up + GELU: h = gelu(xm @ w1 + b1)
    tgemm<1><<<dim3(MLPD / 128, 4096 / 128), 256, GSM_BYTES>>>(
        xm, w1, b1, nullptr, nullptr, 0, hbuf, BB * SS, MLPD, DD);

    // 9) MLP down + gated residual: out = x1 + gate_mlp (seg5) * (h @ w2 + b2)
    tgemm<2><<<dim3(1024 / 128, 4096 / 128), 256, GSM_BYTES>>>(
        hbuf, w2, b2, x1, mod, 5 * DD, out, BB * SS, DD, MLPD);
}

// round 6
// speedup vs baseline: 3.1502x; 1.5434x over previous
#include <cuda_runtime.h>
#include <cuda_bf16.h>
#include <cstdint>
#include <math.h>

// Problem constants
#define BB 4
#define SS 1024
#define DD 1024
#define HH 16
#define HD 64
#define MLPD 4096
#define MODW 6144   // 6*D
#define LN_EPS 1e-5f

// ---------------- scratch (no allocs allowed) ----------------
__device__ float g_mod[BB * MODW];
__device__ float g_xm[(size_t)BB * SS * DD];
__device__ float g_qkv[(size_t)BB * SS * 3 * DD];
__device__ float g_attn[(size_t)BB * SS * DD];
__device__ float g_x1[(size_t)BB * SS * DD];
__device__ float g_h[(size_t)BB * SS * MLPD];
__device__ float g_vt[(size_t)BB * HH * HD * SS];        // V transposed [b][h][d][s]
// tf32-rounded weight copies
__device__ float g_wqkv_r[(size_t)DD * 3 * DD];
__device__ float g_wout_r[(size_t)DD * DD];
__device__ float g_w1_r[(size_t)DD * MLPD];
__device__ float g_w2_r[(size_t)MLPD * DD];

__device__ __forceinline__ float to_tf32(float x) {
    unsigned int u;
    asm("cvt.rna.tf32.f32 %0, %1;" : "=r"(u) : "f"(x));
    return __uint_as_float(u);
}

// ---------------- weight rounding (rna -> tf32 bit pattern, stored as fp32) ----
__global__ void round_kernel(const float* __restrict__ src, float* __restrict__ dst, int n) {
    int i = (blockIdx.x * blockDim.x + threadIdx.x) * 4;
    if (i >= n) return;
    float4 v = *(const float4*)(src + i);
    v.x = to_tf32(v.x); v.y = to_tf32(v.y); v.z = to_tf32(v.z); v.w = to_tf32(v.w);
    *(float4*)(dst + i) = v;
}

// ---------------- adaLN modulation: mod = c @ adaLN_w + adaLN_b ----------------
__global__ void mod_kernel(const float* __restrict__ c, const float* __restrict__ w,
                           const float* __restrict__ bias, float* __restrict__ mod) {
    int n = blockIdx.x * blockDim.x + threadIdx.x;
    if (n >= BB * MODW) return;
    int b = n / MODW;
    int col = n - b * MODW;
    float acc = bias[col];
    const float* cb = c + b * 128;
#pragma unroll 8
    for (int k = 0; k < 128; k++) acc = fmaf(cb[k], w[(size_t)k * MODW + col], acc);
    mod[n] = acc;
}

// ---------------- fused LayerNorm + modulate (output rna-rounded to tf32) ------
__global__ void ln_mod_kernel(const float* __restrict__ x, const float* __restrict__ w,
                              const float* __restrict__ mod, int shiftSeg, int scaleSeg,
                              float* __restrict__ out) {
    __shared__ float r1[256], r2[256];
    int row = blockIdx.x;
    int b = row >> 10;
    int tid = threadIdx.x;
    const float* xr = x + (size_t)row * DD;
    float s = 0.f, ss = 0.f;
#pragma unroll
    for (int i = tid; i < DD; i += 256) {
        float v = xr[i];
        s += v; ss += v * v;
    }
    r1[tid] = s; r2[tid] = ss;
    __syncthreads();
    for (int o = 128; o > 0; o >>= 1) {
        if (tid < o) { r1[tid] += r1[tid + o]; r2[tid] += r2[tid + o]; }
        __syncthreads();
    }
    float mu = r1[0] * (1.0f / DD);
    float var = r2[0] * (1.0f / DD) - mu * mu;
    float rstd = rsqrtf(var + LN_EPS);
    const float* sh = mod + (size_t)b * MODW + shiftSeg * DD;
    const float* sc = mod + (size_t)b * MODW + scaleSeg * DD;
    float* orow = out + (size_t)row * DD;
#pragma unroll
    for (int i = tid; i < DD; i += 256) {
        float y = (xr[i] - mu) * rstd * w[i];
        orow[i] = to_tf32(fmaf(y, 1.0f + sc[i], sh[i]));
    }
}

__device__ __forceinline__ float gelu_tanh(float x) {
    float x3 = x * x * x;
    return 0.5f * x * (1.0f + tanhf(0.7978845608028654f * (x + 0.044715f * x3)));
}

__device__ __forceinline__ void mma_tf32(float c[4], unsigned int a0, unsigned int a1,
                                         unsigned int a2, unsigned int a3,
                                         unsigned int b0, unsigned int b1) {
    asm volatile("mma.sync.aligned.m16n8k8.row.col.f32.tf32.tf32.f32 "
                 "{%0,%1,%2,%3}, {%4,%5,%6,%7}, {%8,%9}, {%0,%1,%2,%3};"
                 : "+f"(c[0]), "+f"(c[1]), "+f"(c[2]), "+f"(c[3])
                 : "r"(a0), "r"(a1), "r"(a2), "r"(a3), "r"(b0), "r"(b1));
}

__device__ __forceinline__ void cp16(void* s, const void* g) {
    unsigned int sa = (unsigned int)__cvta_generic_to_shared(s);
    asm volatile("cp.async.cg.shared.global [%0], [%1], 16;" :: "r"(sa), "l"(g));
}

// ---------------- TF32 tensor-core GEMM with cp.async 3-stage pipeline --------
// CTA 128x128, K-stage 32, 8 warps (2x4), warp tile 64x32.
// As[m][k] stride 36 (row-major, cp.async-friendly, frag bank = 4*gid+tig)
// Bs[k][n] stride 136 (frag bank = 8*tig+gid)
// Inputs are pre-rounded to tf32 -> no cvt in the kernel.
#define TG_ASTRIDE 36
#define TG_ABUF (128 * TG_ASTRIDE)
#define TG_BSTRIDE 136
#define TG_BBUF (32 * TG_BSTRIDE)
#define TG_STAGE (TG_ABUF + TG_BBUF)
#define TG_BYTES (3 * TG_STAGE * 4)

template<int EPI>
__global__ __launch_bounds__(256, 2)
void tgemm(const float* __restrict__ A, const float* __restrict__ B,
           const float* __restrict__ bias, const float* __restrict__ resid,
           const float* __restrict__ mod, int modOff,
           float* __restrict__ C, int M, int N, int K) {
    extern __shared__ float smf[];
    const int tid = threadIdx.x;
    const int lane = tid & 31, wid = tid >> 5;
    const int gid = lane >> 2, tig = lane & 3;
    const int bx = blockIdx.x, by = blockIdx.y;
    const int m0w = (wid >> 2) * 64;
    const int n0w = (wid & 3) * 32;

    const float* Ag = A + (size_t)(by * 128) * K;
    const float* Bg = B + bx * 128;

    float acc[4][4][4];
#pragma unroll
    for (int i = 0; i < 4; i++)
#pragma unroll
        for (int j = 0; j < 4; j++)
#pragma unroll
            for (int r = 0; r < 4; r++) acc[i][j][r] = 0.f;

    const int NS = K >> 5;

    auto issue = [&](int ks) {
        float* As = smf + (ks % 3) * TG_STAGE;
        float* Bs = As + TG_ABUF;
#pragma unroll
        for (int e = 0; e < 4; e++) {
            int cidx = tid + e * 256;
            int m = cidx >> 3, kq = (cidx & 7) * 4;
            cp16(&As[m * TG_ASTRIDE + kq], Ag + (size_t)m * K + ks * 32 + kq);
        }
#pragma unroll
        for (int e = 0; e < 4; e++) {
            int cidx = tid + e * 256;
            int k = cidx >> 5, nq = (cidx & 31) * 4;
            cp16(&Bs[k * TG_BSTRIDE + nq], Bg + (size_t)(ks * 32 + k) * N + nq);
        }
        asm volatile("cp.async.commit_group;");
    };

    issue(0); issue(1); issue(2);

    for (int ks = 0; ks < NS; ks++) {
        if (ks < NS - 2) asm volatile("cp.async.wait_group 2;" ::: "memory");
        else             asm volatile("cp.async.wait_group 0;" ::: "memory");
        __syncthreads();
        const float* As = smf + (ks % 3) * TG_STAGE;
        const float* Bs = As + TG_ABUF;
#pragma unroll
        for (int t = 0; t < 4; t++) {
            const int kb = t * 8;
            unsigned int af[4][4], bf[4][2];
#pragma unroll
            for (int mt = 0; mt < 4; mt++)
#pragma unroll
                for (int r = 0; r < 4; r++)
                    af[mt][r] = __float_as_uint(
                        As[(m0w + mt * 16 + gid + 8 * (r & 1)) * TG_ASTRIDE + kb + tig + 4 * (r >> 1)]);
#pragma unroll
            for (int nt = 0; nt < 4; nt++)
#pragma unroll
                for (int r = 0; r < 2; r++)
                    bf[nt][r] = __float_as_uint(
                        Bs[(kb + tig + 4 * r) * TG_BSTRIDE + n0w + nt * 8 + gid]);
#pragma unroll
            for (int mt = 0; mt < 4; mt++)
#pragma unroll
                for (int nt = 0; nt < 4; nt++)
                    mma_tf32(acc[mt][nt], af[mt][0], af[mt][1], af[mt][2], af[mt][3],
                             bf[nt][0], bf[nt][1]);
        }
        __syncthreads();
        if (ks + 3 < NS) issue(ks + 3);
    }

    // ---- epilogue ----
#pragma unroll
    for (int mt = 0; mt < 4; mt++) {
#pragma unroll
        for (int half = 0; half < 2; half++) {
            int row = by * 128 + m0w + mt * 16 + gid + 8 * half;
            size_t rowBase = (size_t)row * N;
#pragma unroll
            for (int nt = 0; nt < 4; nt++) {
                int col = bx * 128 + n0w + nt * 8 + 2 * tig;
                float v0 = acc[mt][nt][2 * half];
                float v1 = acc[mt][nt][2 * half + 1];
                if (EPI == 0) {
                    *(float2*)&C[rowBase + col] = make_float2(v0, v1);
                } else if (EPI == 1) {
                    v0 = to_tf32(gelu_tanh(v0 + bias[col]));
                    v1 = to_tf32(gelu_tanh(v1 + bias[col + 1]));
                    *(float2*)&C[rowBase + col] = make_float2(v0, v1);
                } else {
                    if (bias) { v0 += bias[col]; v1 += bias[col + 1]; }
                    size_t mb = (size_t)(row >> 10) * MODW + modOff + col;
                    float g0 = mod[mb], g1 = mod[mb + 1];
                    float2 rr = *(const float2*)&resid[rowBase + col];
                    *(float2*)&C[rowBase + col] =
                        make_float2(fmaf(g0, v0, rr.x), fmaf(g1, v1, rr.y));
                }
            }
        }
    }
}

// ---------------- RoPE on q and k (in place in g_qkv) ----------------
__global__ void rope_kernel(float* __restrict__ qkv, const float* __restrict__ cosb,
                            const float* __restrict__ sinb) {
    int id = blockIdx.x * blockDim.x + threadIdx.x;
    if (id >= BB * SS * 2 * HH * 32) return;
    int e = id & 31;
    int h = (id >> 5) & 15;
    int sel = (id >> 9) & 1;
    int bs = id >> 10;
    int s = bs & (SS - 1);
    size_t base = (size_t)bs * 3072 + (size_t)sel * 1024 + h * 64;
    float t1 = qkv[base + e];
    float t2 = qkv[base + e + 32];
    float cv = cosb[s * 32 + e];
    float sv = sinb[s * 32 + e];
    qkv[base + e]      = t1 * cv - t2 * sv;
    qkv[base + e + 32] = t2 * cv + t1 * sv;
}

// ---------------- V transpose: qkv v-part -> vt[b][h][d][s], tf32-rounded -----
__global__ void vtrans_kernel(const float* __restrict__ qkv, float* __restrict__ vt) {
    __shared__ float t[32][33];
    int b = blockIdx.z;
    int s0 = blockIdx.x * 32, hd0 = blockIdx.y * 32;
    int tx = threadIdx.x, ty = threadIdx.y;
#pragma unroll
    for (int j = ty; j < 32; j += 8)
        t[j][tx] = qkv[(size_t)(b * 1024 + s0 + j) * 3072 + 2048 + hd0 + tx];
    __syncthreads();
#pragma unroll
    for (int j = ty; j < 32; j += 8)
        vt[(size_t)(b * 1024 + hd0 + j) * 1024 + s0 + tx] = to_tf32(t[tx][j]);
}

// ---------------- attention: flash-style with tf32 mma ----------------
// CTA: 128 threads (4 warps), 64 q-rows, 64-key tiles. Warp = 16 q x 64.
// Qs[q][d], Ks[key][d], Ps[q][key], Vs[d][key]  (all stride 72)
#define AT_STRIDE 72
#define AT_SMEM_BYTES (4 * 64 * AT_STRIDE * 4)

__global__ __launch_bounds__(128, 3)
void attn_mma_kernel(const float* __restrict__ qkv, const float* __restrict__ vt,
                     float* __restrict__ out) {
    extern __shared__ float sm[];
    float* Qs = sm;
    float* Ks = Qs + 64 * AT_STRIDE;
    float* Ps = Ks + 64 * AT_STRIDE;
    float* Vs = Ps + 64 * AT_STRIDE;
    int bh = blockIdx.x;
    int b = bh >> 4, h = bh & 15;
    size_t bS = (size_t)b * SS;
    int q0 = blockIdx.y * 64;
    int tid = threadIdx.x, w = tid >> 5, lane = tid & 31;
    int gid = lane >> 2, tig = lane & 3;

    // load Q tile (scaled by 1/sqrt(64), rounded)
    for (int idx = tid; idx < 64 * 16; idx += 128) {
        int q = idx >> 4, kq = (idx & 15) * 4;
        float4 v = *(const float4*)(qkv + (bS + q0 + q) * 3072 + h * 64 + kq);
        v.x = to_tf32(v.x * 0.125f); v.y = to_tf32(v.y * 0.125f);
        v.z = to_tf32(v.z * 0.125f); v.w = to_tf32(v.w * 0.125f);
        *(float4*)&Qs[q * AT_STRIDE + kq] = v;
    }

    float o[8][4];
#pragma unroll
    for (int nt = 0; nt < 8; nt++)
#pragma unroll
        for (int r = 0; r < 4; r++) o[nt][r] = 0.f;
    float mA = -1e30f, mB = -1e30f, lA = 0.f, lB = 0.f;

    const float* vbase = vt + ((size_t)(b * 1024 + h * 64)) * 1024;

    for (int kt = 0; kt < 16; kt++) {
        int kb0 = kt * 64;
        __syncthreads();
        // stage K [key][d] and V^T [d][key]
        for (int idx = tid; idx < 64 * 16; idx += 128) {
            int r = idx >> 4, kq = (idx & 15) * 4;
            float4 kv = *(const float4*)(qkv + (bS + kb0 + r) * 3072 + 1024 + h * 64 + kq);
            kv.x = to_tf32(kv.x); kv.y = to_tf32(kv.y);
            kv.z = to_tf32(kv.z); kv.w = to_tf32(kv.w);
            *(float4*)&Ks[r * AT_STRIDE + kq] = kv;
            float4 vv = *(const float4*)(vbase + (size_t)r * 1024 + kb0 + kq);
            *(float4*)&Vs[r * AT_STRIDE + kq] = vv;   // r = d index here
        }
        __syncthreads();

        // ---- QK^T: S[16][64] per warp ----
        float s[8][4];
#pragma unroll
        for (int nt = 0; nt < 8; nt++)
#pragma unroll
            for (int r = 0; r < 4; r++) s[nt][r] = 0.f;
#pragma unroll
        for (int kb = 0; kb < 64; kb += 8) {
            unsigned int af[4];
            af[0] = __float_as_uint(Qs[(w * 16 + gid) * AT_STRIDE + kb + tig]);
            af[1] = __float_as_uint(Qs[(w * 16 + gid + 8) * AT_STRIDE + kb + tig]);
            af[2] = __float_as_uint(Qs[(w * 16 + gid) * AT_STRIDE + kb + tig + 4]);
            af[3] = __float_as_uint(Qs[(w * 16 + gid + 8) * AT_STRIDE + kb + tig + 4]);
#pragma unroll
            for (int nt = 0; nt < 8; nt++) {
                unsigned int b0 = __float_as_uint(Ks[(nt * 8 + gid) * AT_STRIDE + kb + tig]);
                unsigned int b1 = __float_as_uint(Ks[(nt * 8 + gid) * AT_STRIDE + kb + tig + 4]);
                mma_tf32(s[nt], af[0], af[1], af[2], af[3], b0, b1);
            }
        }

        // ---- online softmax (rows gid and gid+8 of warp's 16) ----
        float tmA = -1e30f, tmB = -1e30f;
#pragma unroll
        for (int nt = 0; nt < 8; nt++) {
            tmA = fmaxf(tmA, fmaxf(s[nt][0], s[nt][1]));
            tmB = fmaxf(tmB, fmaxf(s[nt][2], s[nt][3]));
        }
        tmA = fmaxf(tmA, __shfl_xor_sync(0xffffffffu, tmA, 1));
        tmA = fmaxf(tmA, __shfl_xor_sync(0xffffffffu, tmA, 2));
        tmB = fmaxf(tmB, __shfl_xor_sync(0xffffffffu, tmB, 1));
        tmB = fmaxf(tmB, __shfl_xor_sync(0xffffffffu, tmB, 2));
        float nmA = fmaxf(mA, tmA), nmB = fmaxf(mB, tmB);
        float corrA = __expf(mA - nmA), corrB = __expf(mB - nmB);
        mA = nmA; mB = nmB;
        float sumA = 0.f, sumB = 0.f;
#pragma unroll
        for (int nt = 0; nt < 8; nt++) {
            s[nt][0] = __expf(s[nt][0] - nmA);
            s[nt][1] = __expf(s[nt][1] - nmA);
            s[nt][2] = __expf(s[nt][2] - nmB);
            s[nt][3] = __expf(s[nt][3] - nmB);
            sumA += s[nt][0] + s[nt][1];
            sumB += s[nt][2] + s[nt][3];
        }
        sumA += __shfl_xor_sync(0xffffffffu, sumA, 1);
        sumA += __shfl_xor_sync(0xffffffffu, sumA, 2);
        sumB += __shfl_xor_sync(0xffffffffu, sumB, 1);
        sumB += __shfl_xor_sync(0xffffffffu, sumB, 2);
        lA = lA * corrA + sumA;
        lB = lB * corrB + sumB;
#pragma unroll
        for (int nt = 0; nt < 8; nt++) {
            o[nt][0] *= corrA; o[nt][1] *= corrA;
            o[nt][2] *= corrB; o[nt][3] *= corrB;
        }
        // store P (rounded) to Ps[q][key]
#pragma unroll
        for (int nt = 0; nt < 8; nt++) {
            *(float2*)&Ps[(w * 16 + gid) * AT_STRIDE + nt * 8 + 2 * tig] =
                make_float2(to_tf32(s[nt][0]), to_tf32(s[nt][1]));
            *(float2*)&Ps[(w * 16 + gid + 8) * AT_STRIDE + nt * 8 + 2 * tig] =
                make_float2(to_tf32(s[nt][2]), to_tf32(s[nt][3]));
        }
        __syncwarp();

        // ---- PV: o += P[16x64] @ V[64x64] ----
#pragma unroll
        for (int kc = 0; kc < 64; kc += 8) {
            unsigned int af[4];
            af[0] = __float_as_uint(Ps[(w * 16 + gid) * AT_STRIDE + kc + tig]);
            af[1] = __float_as_uint(Ps[(w * 16 + gid + 8) * AT_STRIDE + kc + tig]);
            af[2] = __float_as_uint(Ps[(w * 16 + gid) * AT_STRIDE + kc + tig + 4]);
            af[3] = __float_as_uint(Ps[(w * 16 + gid + 8) * AT_STRIDE + kc + tig + 4]);
#pragma unroll
            for (int nt = 0; nt < 8; nt++) {
                unsigned int b0 = __float_as_uint(Vs[(nt * 8 + gid) * AT_STRIDE + kc + tig]);
                unsigned int b1 = __float_as_uint(Vs[(nt * 8 + gid) * AT_STRIDE + kc + tig + 4]);
                mma_tf32(o[nt], af[0], af[1], af[2], af[3], b0, b1);
            }
        }
    }

    // ---- epilogue: normalize + store (rounded: feeds out-proj GEMM) ----
    float invA = 1.0f / lA, invB = 1.0f / lB;
    size_t rowA = (bS + q0 + w * 16 + gid) * 1024 + h * 64;
    size_t rowB = (bS + q0 + w * 16 + gid + 8) * 1024 + h * 64;
#pragma unroll
    for (int nt = 0; nt < 8; nt++) {
        int col = nt * 8 + 2 * tig;
        *(float2*)&out[rowA + col] =
            make_float2(to_tf32(o[nt][0] * invA), to_tf32(o[nt][1] * invA));
        *(float2*)&out[rowB + col] =
            make_float2(to_tf32(o[nt][2] * invB), to_tf32(o[nt][3] * invB));
    }
}

// ---------------- launch ----------------
extern "C" void kernel_launch(void* const* d_in, const int* in_sizes, int n_in,
                              void* d_out, int out_size) {
    const float* x       = (const float*)d_in[0];
    const float* c       = (const float*)d_in[1];
    const float* norm1_w = (const float*)d_in[2];
    const float* norm2_w = (const float*)d_in[3];
    const float* w_qkv   = (const float*)d_in[4];
    const float* w_out   = (const float*)d_in[5];
    const float* w1      = (const float*)d_in[6];
    const float* b1      = (const float*)d_in[7];
    const float* w2      = (const float*)d_in[8];
    const float* b2      = (const float*)d_in[9];
    const float* adaLN_w = (const float*)d_in[10];
    const float* adaLN_b = (const float*)d_in[11];
    const float* cosb    = (const float*)d_in[12];
    const float* sinb    = (const float*)d_in[13];
    float* out = (float*)d_out;

    float *mod, *xm, *qkv, *attn, *x1, *hbuf, *vt;
    float *wqkv_r, *wout_r, *w1_r, *w2_r;
    cudaGetSymbolAddress((void**)&mod,  g_mod);
    cudaGetSymbolAddress((void**)&xm,   g_xm);
    cudaGetSymbolAddress((void**)&qkv,  g_qkv);
    cudaGetSymbolAddress((void**)&attn, g_attn);
    cudaGetSymbolAddress((void**)&x1,   g_x1);
    cudaGetSymbolAddress((void**)&hbuf, g_h);
    cudaGetSymbolAddress((void**)&vt,   g_vt);
    cudaGetSymbolAddress((void**)&wqkv_r, g_wqkv_r);
    cudaGetSymbolAddress((void**)&wout_r, g_wout_r);
    cudaGetSymbolAddress((void**)&w1_r,   g_w1_r);
    cudaGetSymbolAddress((void**)&w2_r,   g_w2_r);

    cudaFuncSetAttribute(attn_mma_kernel, cudaFuncAttributeMaxDynamicSharedMemorySize,
                         AT_SMEM_BYTES);
    cudaFuncSetAttribute(tgemm<0>, cudaFuncAttributeMaxDynamicSharedMemorySize, TG_BYTES);
    cudaFuncSetAttribute(tgemm<1>, cudaFuncAttributeMaxDynamicSharedMemorySize, TG_BYTES);
    cudaFuncSetAttribute(tgemm<2>, cudaFuncAttributeMaxDynamicSharedMemorySize, TG_BYTES);

    // 0) round weights to tf32 (rna) once per call
    round_kernel<<<(DD * 3 * DD / 4 + 255) / 256, 256>>>(w_qkv, wqkv_r, DD * 3 * DD);
    round_kernel<<<(DD * DD / 4 + 255) / 256, 256>>>(w_out, wout_r, DD * DD);
    round_kernel<<<(DD * MLPD / 4 + 255) / 256, 256>>>(w1, w1_r, DD * MLPD);
    round_kernel<<<(MLPD * DD / 4 + 255) / 256, 256>>>(w2, w2_r, MLPD * DD);

    // 1) adaLN modulation vector
    mod_kernel<<<(BB * MODW + 255) / 256, 256>>>(c, adaLN_w, adaLN_b, mod);

    // 2) LN1 + modulate (shift_msa = seg0, scale_msa = seg1)
    ln_mod_kernel<<<BB * SS, 256>>>(x, norm1_w, mod, 0, 1, xm);

    // 3) QKV GEMM
    tgemm<0><<<dim3(3072 / 128, 4096 / 128), 256, TG_BYTES>>>(
        xm, wqkv_r, nullptr, nullptr, nullptr, 0, qkv, BB * SS, 3 * DD, DD);

    // 4) RoPE in place on q,k; V transpose to [b][h][d][s]
    rope_kernel<<<(BB * SS * 2 * HH * 32) / 256, 256>>>(qkv, cosb, sinb);
    vtrans_kernel<<<dim3(32, 32, 4), dim3(32, 8)>>>(qkv, vt);

    // 5) attention (tensor cores)
    attn_mma_kernel<<<dim3(BB * HH, SS / 64), 128, AT_SMEM_BYTES>>>(qkv, vt, attn);

    // 6) out-proj + gated residual
    tgemm<2><<<dim3(1024 / 128, 4096 / 128), 256, TG_BYTES>>>(
        attn, wout_r, nullptr, x, mod, 2 * DD, x1, BB * SS, DD, DD);

    // 7) LN2 + modulate (shift_mlp = seg3, scale_mlp = seg4)
    ln_mod_kernel<<<BB * SS, 256>>>(x1, norm2_w, mod, 3, 4, xm);

    // 8) MLP up + GELU
    tgemm<1><<<dim3(MLPD / 128, 4096 / 128), 256, TG_BYTES>>>(
        xm, w1_r, b1, nullptr, nullptr, 0, hbuf, BB * SS, MLPD, DD);

    // 9) MLP down + gated residual
    tgemm<2><<<dim3(1024 / 128, 4096 / 128), 256, TG_BYTES>>>(
        hbuf, w2_r, b2, x1, mod, 5 * DD, out, BB * SS, DD, MLPD);
}

// round 7
// speedup vs baseline: 4.6478x; 1.4754x over previous
#include <cuda_runtime.h>
#include <cuda_bf16.h>
#include <cstdint>
#include <math.h>

// Problem constants
#define BB 4
#define SS 1024
#define DD 1024
#define HH 16
#define HD 64
#define MLPD 4096
#define MODW 6144   // 6*D
#define LN_EPS 1e-5f

typedef __nv_bfloat16 bf16;
typedef __nv_bfloat162 bf162;

// ---------------- scratch (no allocs allowed) ----------------
__device__ float g_mod[BB * MODW];
__device__ bf16  g_xm[(size_t)BB * SS * DD];
__device__ float g_qkv[(size_t)BB * SS * 3 * DD];
__device__ bf16  g_attn[(size_t)BB * SS * DD];
__device__ float g_x1[(size_t)BB * SS * DD];
__device__ bf16  g_h[(size_t)BB * SS * MLPD];
__device__ bf16  g_vt[(size_t)BB * HH * HD * SS];        // V^T [b][h][d][s], bf16
// transposed bf16 weights [N][K]
__device__ bf16 g_wqkv_t[(size_t)3 * DD * DD];
__device__ bf16 g_wout_t[(size_t)DD * DD];
__device__ bf16 g_w1_t[(size_t)MLPD * DD];
__device__ bf16 g_w2_t[(size_t)DD * MLPD];

// ---------------- weight transpose + bf16 convert: src[K][N] -> dst[N][K] -----
__global__ void wtrans_kernel(const float* __restrict__ src, bf16* __restrict__ dst,
                              int K, int N) {
    __shared__ float t[32][33];
    int k0 = blockIdx.x * 32, n0 = blockIdx.y * 32;
    int tx = threadIdx.x, ty = threadIdx.y;
#pragma unroll
    for (int j = ty; j < 32; j += 8)
        t[j][tx] = src[(size_t)(k0 + j) * N + n0 + tx];
    __syncthreads();
#pragma unroll
    for (int j = ty; j < 32; j += 8)
        dst[(size_t)(n0 + j) * K + k0 + tx] = __float2bfloat16_rn(t[tx][j]);
}

// ---------------- adaLN modulation: mod = c @ adaLN_w + adaLN_b ----------------
__global__ void mod_kernel(const float* __restrict__ c, const float* __restrict__ w,
                           const float* __restrict__ bias, float* __restrict__ mod) {
    int n = blockIdx.x * blockDim.x + threadIdx.x;
    if (n >= BB * MODW) return;
    int b = n / MODW;
    int col = n - b * MODW;
    float acc = bias[col];
    const float* cb = c + b * 128;
#pragma unroll 8
    for (int k = 0; k < 128; k++) acc = fmaf(cb[k], w[(size_t)k * MODW + col], acc);
    mod[n] = acc;
}

// ---------------- fused LayerNorm + modulate (bf16 output) ----------------
__global__ void ln_mod_kernel(const float* __restrict__ x, const float* __restrict__ w,
                              const float* __restrict__ mod, int shiftSeg, int scaleSeg,
                              bf16* __restrict__ out) {
    __shared__ float r1[256], r2[256];
    int row = blockIdx.x;
    int b = row >> 10;
    int tid = threadIdx.x;
    const float* xr = x + (size_t)row * DD;
    float s = 0.f, ss = 0.f;
#pragma unroll
    for (int i = tid; i < DD; i += 256) {
        float v = xr[i];
        s += v; ss += v * v;
    }
    r1[tid] = s; r2[tid] = ss;
    __syncthreads();
    for (int o = 128; o > 0; o >>= 1) {
        if (tid < o) { r1[tid] += r1[tid + o]; r2[tid] += r2[tid + o]; }
        __syncthreads();
    }
    float mu = r1[0] * (1.0f / DD);
    float var = r2[0] * (1.0f / DD) - mu * mu;
    float rstd = rsqrtf(var + LN_EPS);
    const float* sh = mod + (size_t)b * MODW + shiftSeg * DD;
    const float* sc = mod + (size_t)b * MODW + scaleSeg * DD;
    bf16* orow = out + (size_t)row * DD;
#pragma unroll
    for (int i = tid; i < DD; i += 256) {
        float y = (xr[i] - mu) * rstd * w[i];
        orow[i] = __float2bfloat16_rn(fmaf(y, 1.0f + sc[i], sh[i]));
    }
}

__device__ __forceinline__ float gelu_tanh(float x) {
    float x3 = x * x * x;
    return 0.5f * x * (1.0f + tanhf(0.7978845608028654f * (x + 0.044715f * x3)));
}

__device__ __forceinline__ void mma_bf16(float c[4], unsigned int a0, unsigned int a1,
                                         unsigned int a2, unsigned int a3,
                                         unsigned int b0, unsigned int b1) {
    asm volatile("mma.sync.aligned.m16n8k16.row.col.f32.bf16.bf16.f32 "
                 "{%0,%1,%2,%3}, {%4,%5,%6,%7}, {%8,%9}, {%0,%1,%2,%3};"
                 : "+f"(c[0]), "+f"(c[1]), "+f"(c[2]), "+f"(c[3])
                 : "r"(a0), "r"(a1), "r"(a2), "r"(a3), "r"(b0), "r"(b1));
}

__device__ __forceinline__ void cp16(void* s, const void* g) {
    unsigned int sa = (unsigned int)__cvta_generic_to_shared(s);
    asm volatile("cp.async.cg.shared.global [%0], [%1], 16;" :: "r"(sa), "l"(g));
}

// ---------------- bf16 tensor-core GEMM, cp.async 3-stage ----------------
// CTA 128x128, K-stage 32, 8 warps (2x4), warp 64x32, mma m16n8k16.
// As[m][k], Bs[n][k], both stride 40 halves (80B -> frag banks {20g+t} distinct,
// 16B aligned rows for cp.async).
// A: bf16 activations [M][K]; Bt: bf16 transposed weights [N][K].
// EPI 0: fp32 C = acc          EPI 1: bf16 C = gelu(acc+bias)
// EPI 2: fp32 C = resid + mod[...] * (acc + bias?)
#define TG_STRIDE 40
#define TG_HBUF (128 * TG_STRIDE)               // halves per operand buffer
#define TG_STAGE (2 * TG_HBUF)                  // halves per stage
#define TG_BYTES (3 * TG_STAGE * 2)             // 61440 B

template<int EPI>
__global__ __launch_bounds__(256, 2)
void tgemm(const bf16* __restrict__ A, const bf16* __restrict__ Bt,
           const float* __restrict__ bias, const float* __restrict__ resid,
           const float* __restrict__ mod, int modOff,
           void* __restrict__ Cv, int M, int N, int K) {
    extern __shared__ bf16 smh[];
    const int tid = threadIdx.x;
    const int lane = tid & 31, wid = tid >> 5;
    const int gid = lane >> 2, tig = lane & 3;
    const int bx = blockIdx.x, by = blockIdx.y;
    const int m0w = (wid >> 2) * 64;
    const int n0w = (wid & 3) * 32;

    const bf16* Ag = A + (size_t)(by * 128) * K;
    const bf16* Bg = Bt + (size_t)(bx * 128) * K;

    float acc[4][4][4];
#pragma unroll
    for (int i = 0; i < 4; i++)
#pragma unroll
        for (int j = 0; j < 4; j++)
#pragma unroll
            for (int r = 0; r < 4; r++) acc[i][j][r] = 0.f;

    const int NS = K >> 5;

    auto issue = [&](int ks) {
        bf16* As = smh + (ks % 3) * TG_STAGE;
        bf16* Bs = As + TG_HBUF;
#pragma unroll
        for (int e = 0; e < 2; e++) {
            int idx = tid + e * 256;            // [0,512)
            int row = idx >> 2, q = idx & 3;
            cp16(&As[row * TG_STRIDE + q * 8], Ag + (size_t)row * K + ks * 32 + q * 8);
        }
#pragma unroll
        for (int e = 0; e < 2; e++) {
            int idx = tid + e * 256;
            int row = idx >> 2, q = idx & 3;
            cp16(&Bs[row * TG_STRIDE + q * 8], Bg + (size_t)row * K + ks * 32 + q * 8);
        }
        asm volatile("cp.async.commit_group;");
    };

    issue(0); issue(1); issue(2);

    for (int ks = 0; ks < NS; ks++) {
        if (ks < NS - 2) asm volatile("cp.async.wait_group 2;" ::: "memory");
        else             asm volatile("cp.async.wait_group 0;" ::: "memory");
        __syncthreads();
        const bf16* As = smh + (ks % 3) * TG_STAGE;
        const bf16* Bs = As + TG_HBUF;
#pragma unroll
        for (int t = 0; t < 2; t++) {
            const int K0 = t * 16;
            unsigned int af[4][4], bf[4][2];
#pragma unroll
            for (int mt = 0; mt < 4; mt++) {
                int r0 = m0w + mt * 16 + gid;
                af[mt][0] = *(const unsigned int*)&As[r0 * TG_STRIDE + K0 + 2 * tig];
                af[mt][1] = *(const unsigned int*)&As[(r0 + 8) * TG_STRIDE + K0 + 2 * tig];
                af[mt][2] = *(const unsigned int*)&As[r0 * TG_STRIDE + K0 + 8 + 2 * tig];
                af[mt][3] = *(const unsigned int*)&As[(r0 + 8) * TG_STRIDE + K0 + 8 + 2 * tig];
            }
#pragma unroll
            for (int nt = 0; nt < 4; nt++) {
                int rn = n0w + nt * 8 + gid;
                bf[nt][0] = *(const unsigned int*)&Bs[rn * TG_STRIDE + K0 + 2 * tig];
                bf[nt][1] = *(const unsigned int*)&Bs[rn * TG_STRIDE + K0 + 8 + 2 * tig];
            }
#pragma unroll
            for (int mt = 0; mt < 4; mt++)
#pragma unroll
                for (int nt = 0; nt < 4; nt++)
                    mma_bf16(acc[mt][nt], af[mt][0], af[mt][1], af[mt][2], af[mt][3],
                             bf[nt][0], bf[nt][1]);
        }
        __syncthreads();
        if (ks + 3 < NS) issue(ks + 3);
    }

    // ---- epilogue ----
#pragma unroll
    for (int mt = 0; mt < 4; mt++) {
#pragma unroll
        for (int half = 0; half < 2; half++) {
            int row = by * 128 + m0w + mt * 16 + gid + 8 * half;
            size_t rowBase = (size_t)row * N;
#pragma unroll
            for (int nt = 0; nt < 4; nt++) {
                int col = bx * 128 + n0w + nt * 8 + 2 * tig;
                float v0 = acc[mt][nt][2 * half];
                float v1 = acc[mt][nt][2 * half + 1];
                if (EPI == 0) {
                    *(float2*)&((float*)Cv)[rowBase + col] = make_float2(v0, v1);
                } else if (EPI == 1) {
                    v0 = gelu_tanh(v0 + bias[col]);
                    v1 = gelu_tanh(v1 + bias[col + 1]);
                    *(bf162*)&((bf16*)Cv)[rowBase + col] = __floats2bfloat162_rn(v0, v1);
                } else {
                    if (bias) { v0 += bias[col]; v1 += bias[col + 1]; }
                    size_t mb = (size_t)(row >> 10) * MODW + modOff + col;
                    float g0 = mod[mb], g1 = mod[mb + 1];
                    float2 rr = *(const float2*)&resid[rowBase + col];
                    *(float2*)&((float*)Cv)[rowBase + col] =
                        make_float2(fmaf(g0, v0, rr.x), fmaf(g1, v1, rr.y));
                }
            }
        }
    }
}

// ---------------- RoPE on q and k (in place in g_qkv, fp32) ----------------
__global__ void rope_kernel(float* __restrict__ qkv, const float* __restrict__ cosb,
                            const float* __restrict__ sinb) {
    int id = blockIdx.x * blockDim.x + threadIdx.x;
    if (id >= BB * SS * 2 * HH * 32) return;
    int e = id & 31;
    int h = (id >> 5) & 15;
    int sel = (id >> 9) & 1;
    int bs = id >> 10;
    int s = bs & (SS - 1);
    size_t base = (size_t)bs * 3072 + (size_t)sel * 1024 + h * 64;
    float t1 = qkv[base + e];
    float t2 = qkv[base + e + 32];
    float cv = cosb[s * 32 + e];
    float sv = sinb[s * 32 + e];
    qkv[base + e]      = t1 * cv - t2 * sv;
    qkv[base + e + 32] = t2 * cv + t1 * sv;
}

// ---------------- V transpose: qkv v-part -> vt[b][h][d][s] bf16 ----------------
__global__ void vtrans_kernel(const float* __restrict__ qkv, bf16* __restrict__ vt) {
    __shared__ float t[32][33];
    int b = blockIdx.z;
    int s0 = blockIdx.x * 32, hd0 = blockIdx.y * 32;
    int tx = threadIdx.x, ty = threadIdx.y;
#pragma unroll
    for (int j = ty; j < 32; j += 8)
        t[j][tx] = qkv[(size_t)(b * 1024 + s0 + j) * 3072 + 2048 + hd0 + tx];
    __syncthreads();
#pragma unroll
    for (int j = ty; j < 32; j += 8)
        vt[(size_t)(b * 1024 + hd0 + j) * 1024 + s0 + tx] = __float2bfloat16_rn(t[tx][j]);
}

// ---------------- attention: flash-style, bf16 mma ----------------
// CTA 128 threads (4 warps), 64 q rows, 64-key tiles, warp = 16q x 64.
// Qs[q][d], Ks[key][d], Ps[q][key], Vs[d][key], all bf16 stride 72 halves.
#define AT_STRIDE 72
#define AT_HBUF (64 * AT_STRIDE)
#define AT_SMEM_BYTES (4 * AT_HBUF * 2)

__global__ __launch_bounds__(128, 3)
void attn_mma_kernel(const float* __restrict__ qkv, const bf16* __restrict__ vt,
                     bf16* __restrict__ out) {
    extern __shared__ bf16 smh[];
    bf16* Qs = smh;
    bf16* Ks = Qs + AT_HBUF;
    bf16* Ps = Ks + AT_HBUF;
    bf16* Vs = Ps + AT_HBUF;
    int bh = blockIdx.x;
    int b = bh >> 4, h = bh & 15;
    size_t bS = (size_t)b * SS;
    int q0 = blockIdx.y * 64;
    int tid = threadIdx.x, w = tid >> 5, lane = tid & 31;
    int gid = lane >> 2, tig = lane & 3;

    // load Q (scaled 1/8, bf16)
    for (int idx = tid; idx < 1024; idx += 128) {
        int q = idx >> 4, kq = (idx & 15) * 4;
        float4 v = *(const float4*)(qkv + (bS + q0 + q) * 3072 + h * 64 + kq);
        *(bf162*)&Qs[q * AT_STRIDE + kq]     = __floats2bfloat162_rn(v.x * 0.125f, v.y * 0.125f);
        *(bf162*)&Qs[q * AT_STRIDE + kq + 2] = __floats2bfloat162_rn(v.z * 0.125f, v.w * 0.125f);
    }

    float o[8][4];
#pragma unroll
    for (int nt = 0; nt < 8; nt++)
#pragma unroll
        for (int r = 0; r < 4; r++) o[nt][r] = 0.f;
    float mA = -1e30f, mB = -1e30f, lA = 0.f, lB = 0.f;

    const bf16* vbase = vt + ((size_t)(b * 1024 + h * 64)) * 1024;

    for (int kt = 0; kt < 16; kt++) {
        int kb0 = kt * 64;
        __syncthreads();
        // stage K (fp32 -> bf16) and V^T (already bf16)
        for (int idx = tid; idx < 1024; idx += 128) {
            int r = idx >> 4, kq = (idx & 15) * 4;
            float4 kv = *(const float4*)(qkv + (bS + kb0 + r) * 3072 + 1024 + h * 64 + kq);
            *(bf162*)&Ks[r * AT_STRIDE + kq]     = __floats2bfloat162_rn(kv.x, kv.y);
            *(bf162*)&Ks[r * AT_STRIDE + kq + 2] = __floats2bfloat162_rn(kv.z, kv.w);
        }
        for (int idx = tid; idx < 512; idx += 128) {
            int r = idx >> 3, kq = (idx & 7) * 8;        // r = d index, 8 halves
            const uint2* vp = (const uint2*)(vbase + (size_t)r * 1024 + kb0 + kq);
            *(uint2*)&Vs[r * AT_STRIDE + kq]     = vp[0];
            *(uint2*)&Vs[r * AT_STRIDE + kq + 4] = vp[1];
        }
        __syncthreads();

        // ---- QK^T: S[16][64] per warp ----
        float s[8][4];
#pragma unroll
        for (int nt = 0; nt < 8; nt++)
#pragma unroll
            for (int r = 0; r < 4; r++) s[nt][r] = 0.f;
#pragma unroll
        for (int kb = 0; kb < 64; kb += 16) {
            unsigned int af[4];
            int rq = w * 16 + gid;
            af[0] = *(const unsigned int*)&Qs[rq * AT_STRIDE + kb + 2 * tig];
            af[1] = *(const unsigned int*)&Qs[(rq + 8) * AT_STRIDE + kb + 2 * tig];
            af[2] = *(const unsigned int*)&Qs[rq * AT_STRIDE + kb + 8 + 2 * tig];
            af[3] = *(const unsigned int*)&Qs[(rq + 8) * AT_STRIDE + kb + 8 + 2 * tig];
#pragma unroll
            for (int nt = 0; nt < 8; nt++) {
                int rk = nt * 8 + gid;
                unsigned int b0 = *(const unsigned int*)&Ks[rk * AT_STRIDE + kb + 2 * tig];
                unsigned int b1 = *(const unsigned int*)&Ks[rk * AT_STRIDE + kb + 8 + 2 * tig];
                mma_bf16(s[nt], af[0], af[1], af[2], af[3], b0, b1);
            }
        }

        // ---- online softmax (rows gid, gid+8) ----
        float tmA = -1e30f, tmB = -1e30f;
#pragma unroll
        for (int nt = 0; nt < 8; nt++) {
            tmA = fmaxf(tmA, fmaxf(s[nt][0], s[nt][1]));
            tmB = fmaxf(tmB, fmaxf(s[nt][2], s[nt][3]));
        }
        tmA = fmaxf(tmA, __shfl_xor_sync(0xffffffffu, tmA, 1));
        tmA = fmaxf(tmA, __shfl_xor_sync(0xffffffffu, tmA, 2));
        tmB = fmaxf(tmB, __shfl_xor_sync(0xffffffffu, tmB, 1));
        tmB = fmaxf(tmB, __shfl_xor_sync(0xffffffffu, tmB, 2));
        float nmA = fmaxf(mA, tmA), nmB = fmaxf(mB, tmB);
        float corrA = __expf(mA - nmA), corrB = __expf(mB - nmB);
        mA = nmA; mB = nmB;
        float sumA = 0.f, sumB = 0.f;
#pragma unroll
        for (int nt = 0; nt < 8; nt++) {
            s[nt][0] = __expf(s[nt][0] - nmA);
            s[nt][1] = __expf(s[nt][1] - nmA);
            s[nt][2] = __expf(s[nt][2] - nmB);
            s[nt][3] = __expf(s[nt][3] - nmB);
            sumA += s[nt][0] + s[nt][1];
            sumB += s[nt][2] + s[nt][3];
        }
        sumA += __shfl_xor_sync(0xffffffffu, sumA, 1);
        sumA += __shfl_xor_sync(0xffffffffu, sumA, 2);
        sumB += __shfl_xor_sync(0xffffffffu, sumB, 1);
        sumB += __shfl_xor_sync(0xffffffffu, sumB, 2);
        lA = lA * corrA + sumA;
        lB = lB * corrB + sumB;
#pragma unroll
        for (int nt = 0; nt < 8; nt++) {
            o[nt][0] *= corrA; o[nt][1] *= corrA;
            o[nt][2] *= corrB; o[nt][3] *= corrB;
        }
        // store P as bf16 pairs
#pragma unroll
        for (int nt = 0; nt < 8; nt++) {
            int rq = w * 16 + gid;
            *(bf162*)&Ps[rq * AT_STRIDE + nt * 8 + 2 * tig] =
                __floats2bfloat162_rn(s[nt][0], s[nt][1]);
            *(bf162*)&Ps[(rq + 8) * AT_STRIDE + nt * 8 + 2 * tig] =
                __floats2bfloat162_rn(s[nt][2], s[nt][3]);
        }
        __syncwarp();

        // ---- PV: o += P[16x64] @ V^T[64d][64key] ----
#pragma unroll
        for (int kc = 0; kc < 64; kc += 16) {
            unsigned int af[4];
            int rq = w * 16 + gid;
            af[0] = *(const unsigned int*)&Ps[rq * AT_STRIDE + kc + 2 * tig];
            af[1] = *(const unsigned int*)&Ps[(rq + 8) * AT_STRIDE + kc + 2 * tig];
            af[2] = *(const unsigned int*)&Ps[rq * AT_STRIDE + kc + 8 + 2 * tig];
            af[3] = *(const unsigned int*)&Ps[(rq + 8) * AT_STRIDE + kc + 8 + 2 * tig];
#pragma unroll
            for (int nt = 0; nt < 8; nt++) {
                int rd = nt * 8 + gid;
                unsigned int b0 = *(const unsigned int*)&Vs[rd * AT_STRIDE + kc + 2 * tig];
                unsigned int b1 = *(const unsigned int*)&Vs[rd * AT_STRIDE + kc + 8 + 2 * tig];
                mma_bf16(o[nt], af[0], af[1], af[2], af[3], b0, b1);
            }
        }
    }

    // ---- epilogue: normalize + store bf16 (feeds out-proj GEMM) ----
    float invA = 1.0f / lA, invB = 1.0f / lB;
    size_t rowA = (bS + q0 + w * 16 + gid) * 1024 + h * 64;
    size_t rowB = (bS + q0 + w * 16 + gid + 8) * 1024 + h * 64;
#pragma unroll
    for (int nt = 0; nt < 8; nt++) {
        int col = nt * 8 + 2 * tig;
        *(bf162*)&out[rowA + col] = __floats2bfloat162_rn(o[nt][0] * invA, o[nt][1] * invA);
        *(bf162*)&out[rowB + col] = __floats2bfloat162_rn(o[nt][2] * invB, o[nt][3] * invB);
    }
}

// ---------------- launch ----------------
extern "C" void kernel_launch(void* const* d_in, const int* in_sizes, int n_in,
                              void* d_out, int out_size) {
    const float* x       = (const float*)d_in[0];
    const float* c       = (const float*)d_in[1];
    const float* norm1_w = (const float*)d_in[2];
    const float* norm2_w = (const float*)d_in[3];
    const float* w_qkv   = (const float*)d_in[4];
    const float* w_out   = (const float*)d_in[5];
    const float* w1      = (const float*)d_in[6];
    const float* b1      = (const float*)d_in[7];
    const float* w2      = (const float*)d_in[8];
    const float* b2      = (const float*)d_in[9];
    const float* adaLN_w = (const float*)d_in[10];
    const float* adaLN_b = (const float*)d_in[11];
    const float* cosb    = (const float*)d_in[12];
    const float* sinb    = (const float*)d_in[13];
    float* out = (float*)d_out;

    float *mod, *qkv, *x1;
    bf16 *xm, *attn, *hbuf, *vt, *wqkv_t, *wout_t, *w1_t, *w2_t;
    cudaGetSymbolAddress((void**)&mod,  g_mod);
    cudaGetSymbolAddress((void**)&xm,   g_xm);
    cudaGetSymbolAddress((void**)&qkv,  g_qkv);
    cudaGetSymbolAddress((void**)&attn, g_attn);
    cudaGetSymbolAddress((void**)&x1,   g_x1);
    cudaGetSymbolAddress((void**)&hbuf, g_h);
    cudaGetSymbolAddress((void**)&vt,   g_vt);
    cudaGetSymbolAddress((void**)&wqkv_t, g_wqkv_t);
    cudaGetSymbolAddress((void**)&wout_t, g_wout_t);
    cudaGetSymbolAddress((void**)&w1_t,   g_w1_t);
    cudaGetSymbolAddress((void**)&w2_t,   g_w2_t);

    cudaFuncSetAttribute(attn_mma_kernel, cudaFuncAttributeMaxDynamicSharedMemorySize,
                         AT_SMEM_BYTES);
    cudaFuncSetAttribute(tgemm<0>, cudaFuncAttributeMaxDynamicSharedMemorySize, TG_BYTES);
    cudaFuncSetAttribute(tgemm<1>, cudaFuncAttributeMaxDynamicSharedMemorySize, TG_BYTES);
    cudaFuncSetAttribute(tgemm<2>, cudaFuncAttributeMaxDynamicSharedMemorySize, TG_BYTES);

    // 0) transpose + convert weights to bf16 [N][K]
    wtrans_kernel<<<dim3(DD / 32, 3 * DD / 32), dim3(32, 8)>>>(w_qkv, wqkv_t, DD, 3 * DD);
    wtrans_kernel<<<dim3(DD / 32, DD / 32),     dim3(32, 8)>>>(w_out, wout_t, DD, DD);
    wtrans_kernel<<<dim3(DD / 32, MLPD / 32),   dim3(32, 8)>>>(w1, w1_t, DD, MLPD);
    wtrans_kernel<<<dim3(MLPD / 32, DD / 32),   dim3(32, 8)>>>(w2, w2_t, MLPD, DD);

    // 1) adaLN modulation vector
    mod_kernel<<<(BB * MODW + 255) / 256, 256>>>(c, adaLN_w, adaLN_b, mod);

    // 2) LN1 + modulate
    ln_mod_kernel<<<BB * SS, 256>>>(x, norm1_w, mod, 0, 1, xm);

    // 3) QKV GEMM -> fp32 qkv
    tgemm<0><<<dim3(3072 / 128, 4096 / 128), 256, TG_BYTES>>>(
        xm, wqkv_t, nullptr, nullptr, nullptr, 0, qkv, BB * SS, 3 * DD, DD);

    // 4) RoPE (fp32 in place); V transpose -> bf16
    rope_kernel<<<(BB * SS * 2 * HH * 32) / 256, 256>>>(qkv, cosb, sinb);
    vtrans_kernel<<<dim3(32, 32, 4), dim3(32, 8)>>>(qkv, vt);

    // 5) attention (bf16 tensor cores) -> bf16 attn
    attn_mma_kernel<<<dim3(BB * HH, SS / 64), 128, AT_SMEM_BYTES>>>(qkv, vt, attn);

    // 6) out-proj + gated residual -> fp32 x1
    tgemm<2><<<dim3(1024 / 128, 4096 / 128), 256, TG_BYTES>>>(
        attn, wout_t, nullptr, x, mod, 2 * DD, x1, BB * SS, DD, DD);

    // 7) LN2 + modulate
    ln_mod_kernel<<<BB * SS, 256>>>(x1, norm2_w, mod, 3, 4, xm);

    // 8) MLP up + GELU -> bf16 h
    tgemm<1><<<dim3(MLPD / 128, 4096 / 128), 256, TG_BYTES>>>(
        xm, w1_t, b1, nullptr, nullptr, 0, hbuf, BB * SS, MLPD, DD);

    // 9) MLP down + gated residual -> fp32 out
    tgemm<2><<<dim3(1024 / 128, 4096 / 128), 256, TG_BYTES>>>(
        hbuf, w2_t, b2, x1, mod, 5 * DD, out, BB * SS, DD, MLPD);
}